// round 9
// baseline (speedup 1.0000x reference)
#include <cuda_runtime.h>

#define BATCH 128
#define NIN   1024
#define NOUT  512
#define JT    64
#define NJT   (NOUT / JT)    // 8
#define NCH   37             // 36 chunks of 28 + 1 of 16 ; grid 8*37 = 296 = 148*2
#define NBLK  296
#define NTHR  (NBLK * 256)   // 75776
#define SRMAX 14
#define E0    2.1245f
#define LN2   0.69314718f
#define W_F4  131072         // float4 count per w array
#define X_F4  32768          // float4 count of x

__device__ int          g_max_bits;              // zero-init; monotone -> replay-stable
__device__ unsigned int g_gate;                  // arrival counter; reset by k_reduce
__device__ float        g_lvT[NIN * BATCH];      // transposed clamped lg2 input
__device__ float        g_partial[NCH * BATCH * NOUT];

__device__ __forceinline__ float ex2f_(float x) {
    float y; asm("ex2.approx.f32 %0, %1;" : "=f"(y) : "f"(x)); return y;
}
__device__ __forceinline__ float lg2f_(float x) {
    float y; asm("lg2.approx.f32 %0, %1;" : "=f"(y) : "f"(x)); return y;
}

// ---------------------------------------------------------------------------
// Main kernel with cooperative prologue (all 296 CTAs co-resident at occ=2).
// Prologue: slice-scan max|w|, slice-build lvT, then global gate.
// Body: Taylor K=4, register-blocked 4j x 8b per thread (FFMA-bound).
// ---------------------------------------------------------------------------
template<int SR>
__device__ __forceinline__ void stage_rows(
    const float* __restrict__ w_pos, const float* __restrict__ w_neg,
    const float* __restrict__ n_param,
    float* phi_s, float* coef_s,
    int i0, int j0, int tid, int jq, int bbase, float cG, float (*acc)[8])
{
    __syncthreads();
    // ---- stage phi[ii][k][b]
    constexpr int TOT_LV = SR * BATCH;
    #pragma unroll
    for (int r = 0; r < (TOT_LV + 255) / 256; r++) {
        int idx = r * 256 + tid;
        if ((TOT_LV % 256 == 0) || idx < TOT_LV) {
            int ii = idx >> 7;
            int b  = idx & 127;
            float lv = g_lvT[(i0 + ii) * BATCH + b];
            float p0 = ex2f_(E0 * lv);
            float L  = lv * LN2;
            float p1 = p0 * L;
            float p2 = p1 * (L * 0.5f);
            float p3 = p2 * (L * 0.33333333f);
            float* dst = &phi_s[ii * 512 + b];
            dst[0]   = p0;
            dst[128] = p1;
            dst[256] = p2;
            dst[384] = p3;
        }
    }
    // ---- stage C_k at coef[ii][k][j]
    constexpr int TOT_CF = SR * JT;
    #pragma unroll
    for (int r = 0; r < (TOT_CF + 255) / 256; r++) {
        int idx = r * 256 + tid;
        if ((TOT_CF % 256 == 0) || idx < TOT_CF) {
            int ii = idx >> 6, jj = idx & 63;
            int i = i0 + ii, j = j0 + jj;
            float cp = 0.5f * (fabsf(w_pos[i * NOUT + j]) + cG);
            float cn = 0.5f * (fabsf(w_neg[i * NOUT + j]) + cG);
            float2 np = reinterpret_cast<const float2*>(n_param)[i * NOUT + j];
            float ep = lg2f_(np.x) + 1.0f - E0;
            float en = lg2f_(np.y) + 1.0f - E0;
            float* dst = &coef_s[ii * 256 + jj];
            dst[0]   = cp - cn;
            dst[64]  = cp * ep - cn * en;
            dst[128] = cp * ep * ep - cn * en * en;
            dst[192] = cp * ep * ep * ep - cn * en * en * en;
        }
    }
    __syncthreads();

    // ---- inner loop: 12 LDS.128 / 128 FFMA per thread*ii -> FFMA-bound
    #pragma unroll 2
    for (int ii = 0; ii < SR; ii++) {
        const float* cb = &coef_s[ii * 256 + jq * 4];
        const float* pb = &phi_s[ii * 512 + bbase];
        #pragma unroll
        for (int k = 0; k < 4; k++) {
            float4 c  = *reinterpret_cast<const float4*>(cb + k * 64);
            float4 pa = *reinterpret_cast<const float4*>(pb + k * 128);
            float4 pc = *reinterpret_cast<const float4*>(pb + k * 128 + 4);
            const float cv[4] = {c.x, c.y, c.z, c.w};
            const float pv[8] = {pa.x, pa.y, pa.z, pa.w, pc.x, pc.y, pc.z, pc.w};
            #pragma unroll
            for (int j = 0; j < 4; j++)
                #pragma unroll
                for (int b = 0; b < 8; b++)
                    acc[j][b] = fmaf(cv[j], pv[b], acc[j][b]);
        }
    }
}

__global__ void __launch_bounds__(256, 2)
k_main(const float4* __restrict__ x4,
       const float* __restrict__ w_pos, const float* __restrict__ w_neg,
       const float* __restrict__ n_param) {
    __shared__ __align__(16) float phi_s[SRMAX * 4 * BATCH];   // 28 KB
    __shared__ __align__(16) float coef_s[SRMAX * 4 * JT];     // 14 KB

    const int tid = threadIdx.x;
    const int bid = blockIdx.y * NJT + blockIdx.x;
    const int g   = bid * 256 + tid;

    // ================= cooperative prologue =================
    const float4* wp4 = reinterpret_cast<const float4*>(w_pos);
    const float4* wn4 = reinterpret_cast<const float4*>(w_neg);
    float m = 0.5f;   // bias value always present
    for (int idx = g; idx < 2 * W_F4; idx += NTHR) {
        float4 a = (idx < W_F4) ? wp4[idx] : wn4[idx - W_F4];
        m = fmaxf(m, fmaxf(fmaxf(fabsf(a.x), fabsf(a.y)),
                           fmaxf(fabsf(a.z), fabsf(a.w))));
    }
    for (int idx = g; idx < X_F4; idx += NTHR) {
        float4 xv = x4[idx];
        int b = idx >> 8;
        int i = (idx & 255) * 4;
        g_lvT[(i + 0) * BATCH + b] = fmaxf(lg2f_(2.0f * fminf(fmaxf(xv.x, 0.0f), 1.0f)), -8.0f);
        g_lvT[(i + 1) * BATCH + b] = fmaxf(lg2f_(2.0f * fminf(fmaxf(xv.y, 0.0f), 1.0f)), -8.0f);
        g_lvT[(i + 2) * BATCH + b] = fmaxf(lg2f_(2.0f * fminf(fmaxf(xv.z, 0.0f), 1.0f)), -8.0f);
        g_lvT[(i + 3) * BATCH + b] = fmaxf(lg2f_(2.0f * fminf(fmaxf(xv.w, 0.0f), 1.0f)), -8.0f);
    }
    #pragma unroll
    for (int o = 16; o; o >>= 1) m = fmaxf(m, __shfl_xor_sync(0xffffffffu, m, o));
    {
        float* sm = coef_s;   // reuse before staging
        const int lane = tid & 31, w = tid >> 5;
        if (lane == 0) sm[w] = m;
        __syncthreads();
        if (tid == 0) {
            #pragma unroll
            for (int i = 1; i < 8; i++) m = fmaxf(m, sm[i]);
            atomicMax(&g_max_bits, __float_as_int(m));
            __threadfence();
            atomicAdd(&g_gate, 1u);
            while (*reinterpret_cast<volatile unsigned int*>(&g_gate) < NBLK)
                __nanosleep(32);
        }
    }
    __syncthreads();
    __threadfence();
    // ================= end prologue =================

    const int jq    = tid & 15;
    const int bbase = (tid >> 4) * 8;
    const int j0    = blockIdx.x * JT;
    const int ch    = blockIdx.y;
    const float cG  = __int_as_float(g_max_bits) * (1.0f / 9.0f);

    float acc[4][8];
    #pragma unroll
    for (int j = 0; j < 4; j++)
        #pragma unroll
        for (int b = 0; b < 8; b++) acc[j][b] = 0.0f;

    if (ch < 36) {
        int i0 = ch * 28;
        stage_rows<14>(w_pos, w_neg, n_param, phi_s, coef_s, i0,      j0, tid, jq, bbase, cG, acc);
        stage_rows<14>(w_pos, w_neg, n_param, phi_s, coef_s, i0 + 14, j0, tid, jq, bbase, cG, acc);
    } else {
        stage_rows<8>(w_pos, w_neg, n_param, phi_s, coef_s, 1008, j0, tid, jq, bbase, cG, acc);
        stage_rows<8>(w_pos, w_neg, n_param, phi_s, coef_s, 1016, j0, tid, jq, bbase, cG, acc);
    }

    float* outp = &g_partial[ch * (BATCH * NOUT)];
    #pragma unroll
    for (int b = 0; b < 8; b++) {
        float4 v = make_float4(acc[0][b], acc[1][b], acc[2][b], acc[3][b]);
        *reinterpret_cast<float4*>(&outp[(bbase + b) * NOUT + j0 + jq * 4]) = v;
    }
}

// ---------------------------------------------------------------------------
// Reduction: 256 blocks x 256 threads; 4-way chunk split per output float4,
// deterministic fixed-order combine via SMEM; exact bias term fused.
// Partials are L2-resident (9.7MB just written) -> LTS-throughput bound.
// ---------------------------------------------------------------------------
__global__ void __launch_bounds__(256)
k_reduce(float4* __restrict__ out,
         const float* __restrict__ b_pos,
         const float* __restrict__ b_neg,
         const float* __restrict__ n_param) {
    __shared__ float4 sm[256];
    const int tid = threadIdx.x;
    const int s   = tid >> 6;           // chunk-slice 0..3
    const int ol  = tid & 63;           // output f4 within block
    const int o   = blockIdx.x * 64 + ol;    // 0..16383
    if (blockIdx.x == 0 && tid == 0) g_gate = 0;   // replay reset

    const float4* gp = reinterpret_cast<const float4*>(g_partial);
    const int c0 = (s == 0) ? 0 : 10 + (s - 1) * 9;
    const int nc = (s == 0) ? 10 : 9;
    float4 a = make_float4(0.0f, 0.0f, 0.0f, 0.0f);
    #pragma unroll 10
    for (int c = 0; c < nc; c++) {
        float4 v = gp[(c0 + c) * (BATCH * NOUT / 4) + o];
        a.x += v.x; a.y += v.y; a.z += v.z; a.w += v.w;
    }
    sm[tid] = a;
    __syncthreads();

    if (s == 0) {
        float4 s1 = sm[64 + ol], s2 = sm[128 + ol], s3 = sm[192 + ol];
        a = sm[ol];
        a.x = ((a.x + s1.x) + s2.x) + s3.x;
        a.y = ((a.y + s1.y) + s2.y) + s3.y;
        a.z = ((a.z + s1.z) + s2.z) + s3.z;
        a.w = ((a.w + s1.w) + s2.w) + s3.w;

        const int j = (o * 4) & (NOUT - 1);
        const float cG = __int_as_float(g_max_bits) * (1.0f / 9.0f);
        float4 bp = *reinterpret_cast<const float4*>(&b_pos[j]);
        float4 bn = *reinterpret_cast<const float4*>(&b_neg[j]);
        const float* nrow = n_param + (size_t)NIN * (2 * NOUT);
        float4 n0 = *reinterpret_cast<const float4*>(&nrow[2 * j]);
        float4 n1 = *reinterpret_cast<const float4*>(&nrow[2 * j + 4]);
        a.x += (fabsf(bp.x) + cG) * n0.x - (fabsf(bn.x) + cG) * n0.y;
        a.y += (fabsf(bp.y) + cG) * n0.z - (fabsf(bn.y) + cG) * n0.w;
        a.z += (fabsf(bp.z) + cG) * n1.x - (fabsf(bn.z) + cG) * n1.y;
        a.w += (fabsf(bp.w) + cG) * n1.z - (fabsf(bn.w) + cG) * n1.w;
        out[o] = a;
    }
}

// ---------------------------------------------------------------------------
extern "C" void kernel_launch(void* const* d_in, const int* in_sizes, int n_in,
                              void* d_out, int out_size) {
    const float* x       = (const float*)d_in[0];
    const float* w_pos   = (const float*)d_in[1];
    const float* w_neg   = (const float*)d_in[2];
    const float* b_pos   = (const float*)d_in[3];
    const float* b_neg   = (const float*)d_in[4];
    const float* n_param = (const float*)d_in[5];

    dim3 grid(NJT, NCH);                      // 8 x 37 = 296 = 148*2 (all co-resident)
    k_main<<<grid, 256>>>((const float4*)x, w_pos, w_neg, n_param);
    k_reduce<<<256, 256>>>((float4*)d_out, b_pos, b_neg, n_param);
}

// round 10
// speedup vs baseline: 1.0013x; 1.0013x over previous
#include <cuda_runtime.h>

#define BATCH 128
#define NIN   1024
#define NOUT  512
#define JT    64
#define NJT   (NOUT / JT)    // 8
#define NCH   37             // 36 chunks of 28 + 1 of 16 ; grid 8*37 = 296 = 148*2
#define NBLK  296
#define NTHR  (NBLK * 256)   // 75776
#define SRMAX 14
#define E0    2.1245f
#define LN2   0.69314718f
#define W_F4  131072         // float4 count per w array
#define X_F4  32768          // float4 count of x
#define OUTF4 (BATCH * NOUT / 4)   // 16384

__device__ int          g_max_bits;              // zero-init; monotone -> replay-stable
__device__ unsigned int g_gate1, g_gate2;        // monotone ticket counters (never reset)
__device__ float        g_lvT[NIN * BATCH];      // transposed clamped lg2 input
__device__ float        g_partial[NCH * BATCH * NOUT];

__device__ __forceinline__ float ex2f_(float x) {
    float y; asm("ex2.approx.f32 %0, %1;" : "=f"(y) : "f"(x)); return y;
}
__device__ __forceinline__ float lg2f_(float x) {
    float y; asm("lg2.approx.f32 %0, %1;" : "=f"(y) : "f"(x)); return y;
}

// Monotone-ticket global barrier: each replay consumes exactly NBLK tickets,
// so target = (ticket/NBLK + 1)*NBLK. No reset needed across graph replays.
__device__ __forceinline__ void global_gate(unsigned int* ctr, int tid) {
    __syncthreads();
    if (tid == 0) {
        __threadfence();
        unsigned int t = atomicAdd(ctr, 1u);
        unsigned int target = (t / NBLK + 1u) * NBLK;
        while (*reinterpret_cast<volatile unsigned int*>(ctr) < target)
            __nanosleep(32);
    }
    __syncthreads();
    __threadfence();
}

// ---------------------------------------------------------------------------
// Staged compute: Taylor K=4, register-blocked 4j x 8b per thread (FFMA-bound)
// ---------------------------------------------------------------------------
template<int SR>
__device__ __forceinline__ void stage_rows(
    const float* __restrict__ w_pos, const float* __restrict__ w_neg,
    const float* __restrict__ n_param,
    float* phi_s, float* coef_s,
    int i0, int j0, int tid, int jq, int bbase, float cG, float (*acc)[8])
{
    __syncthreads();
    // ---- stage phi[ii][k][b]
    constexpr int TOT_LV = SR * BATCH;
    #pragma unroll
    for (int r = 0; r < (TOT_LV + 255) / 256; r++) {
        int idx = r * 256 + tid;
        if ((TOT_LV % 256 == 0) || idx < TOT_LV) {
            int ii = idx >> 7;
            int b  = idx & 127;
            float lv = g_lvT[(i0 + ii) * BATCH + b];
            float p0 = ex2f_(E0 * lv);
            float L  = lv * LN2;
            float p1 = p0 * L;
            float p2 = p1 * (L * 0.5f);
            float p3 = p2 * (L * 0.33333333f);
            float* dst = &phi_s[ii * 512 + b];
            dst[0]   = p0;
            dst[128] = p1;
            dst[256] = p2;
            dst[384] = p3;
        }
    }
    // ---- stage C_k at coef[ii][k][j]
    constexpr int TOT_CF = SR * JT;
    #pragma unroll
    for (int r = 0; r < (TOT_CF + 255) / 256; r++) {
        int idx = r * 256 + tid;
        if ((TOT_CF % 256 == 0) || idx < TOT_CF) {
            int ii = idx >> 6, jj = idx & 63;
            int i = i0 + ii, j = j0 + jj;
            float cp = 0.5f * (fabsf(w_pos[i * NOUT + j]) + cG);
            float cn = 0.5f * (fabsf(w_neg[i * NOUT + j]) + cG);
            float2 np = reinterpret_cast<const float2*>(n_param)[i * NOUT + j];
            float ep = lg2f_(np.x) + 1.0f - E0;
            float en = lg2f_(np.y) + 1.0f - E0;
            float* dst = &coef_s[ii * 256 + jj];
            dst[0]   = cp - cn;
            dst[64]  = cp * ep - cn * en;
            dst[128] = cp * ep * ep - cn * en * en;
            dst[192] = cp * ep * ep * ep - cn * en * en * en;
        }
    }
    __syncthreads();

    // ---- inner loop: 12 LDS.128 / 128 FFMA per thread*ii -> FFMA-bound
    #pragma unroll 2
    for (int ii = 0; ii < SR; ii++) {
        const float* cb = &coef_s[ii * 256 + jq * 4];
        const float* pb = &phi_s[ii * 512 + bbase];
        #pragma unroll
        for (int k = 0; k < 4; k++) {
            float4 c  = *reinterpret_cast<const float4*>(cb + k * 64);
            float4 pa = *reinterpret_cast<const float4*>(pb + k * 128);
            float4 pc = *reinterpret_cast<const float4*>(pb + k * 128 + 4);
            const float cv[4] = {c.x, c.y, c.z, c.w};
            const float pv[8] = {pa.x, pa.y, pa.z, pa.w, pc.x, pc.y, pc.z, pc.w};
            #pragma unroll
            for (int j = 0; j < 4; j++)
                #pragma unroll
                for (int b = 0; b < 8; b++)
                    acc[j][b] = fmaf(cv[j], pv[b], acc[j][b]);
        }
    }
}

// ---------------------------------------------------------------------------
// Single persistent kernel: prologue (max|w| scan + lvT) -> gate1 ->
// main compute -> store partials -> gate2 -> L2-hot in-place reduction.
// ---------------------------------------------------------------------------
__global__ void __launch_bounds__(256, 2)
k_all(const float4* __restrict__ x4,
      const float* __restrict__ w_pos, const float* __restrict__ w_neg,
      const float* __restrict__ n_param,
      const float* __restrict__ b_pos, const float* __restrict__ b_neg,
      float4* __restrict__ out) {
    __shared__ __align__(16) float phi_s[SRMAX * 4 * BATCH];   // 28 KB
    __shared__ __align__(16) float coef_s[SRMAX * 4 * JT];     // 14 KB

    const int tid = threadIdx.x;
    const int bid = blockIdx.y * NJT + blockIdx.x;
    const int g   = bid * 256 + tid;

    // ================= prologue =================
    const float4* wp4 = reinterpret_cast<const float4*>(w_pos);
    const float4* wn4 = reinterpret_cast<const float4*>(w_neg);
    float m = 0.5f;   // bias value always present
    for (int idx = g; idx < 2 * W_F4; idx += NTHR) {
        float4 a = (idx < W_F4) ? wp4[idx] : wn4[idx - W_F4];
        m = fmaxf(m, fmaxf(fmaxf(fabsf(a.x), fabsf(a.y)),
                           fmaxf(fabsf(a.z), fabsf(a.w))));
    }
    for (int idx = g; idx < X_F4; idx += NTHR) {
        float4 xv = x4[idx];
        int b = idx >> 8;
        int i = (idx & 255) * 4;
        g_lvT[(i + 0) * BATCH + b] = fmaxf(lg2f_(2.0f * fminf(fmaxf(xv.x, 0.0f), 1.0f)), -8.0f);
        g_lvT[(i + 1) * BATCH + b] = fmaxf(lg2f_(2.0f * fminf(fmaxf(xv.y, 0.0f), 1.0f)), -8.0f);
        g_lvT[(i + 2) * BATCH + b] = fmaxf(lg2f_(2.0f * fminf(fmaxf(xv.z, 0.0f), 1.0f)), -8.0f);
        g_lvT[(i + 3) * BATCH + b] = fmaxf(lg2f_(2.0f * fminf(fmaxf(xv.w, 0.0f), 1.0f)), -8.0f);
    }
    #pragma unroll
    for (int o = 16; o; o >>= 1) m = fmaxf(m, __shfl_xor_sync(0xffffffffu, m, o));
    {
        float* sm = coef_s;
        const int lane = tid & 31, w = tid >> 5;
        if (lane == 0) sm[w] = m;
        __syncthreads();
        if (tid == 0) {
            #pragma unroll
            for (int i = 1; i < 8; i++) m = fmaxf(m, sm[i]);
            atomicMax(&g_max_bits, __float_as_int(m));
        }
    }
    global_gate(&g_gate1, tid);
    // ================= main compute =================

    const int jq    = tid & 15;
    const int bbase = (tid >> 4) * 8;
    const int j0    = blockIdx.x * JT;
    const int ch    = blockIdx.y;
    const float cG  = __int_as_float(g_max_bits) * (1.0f / 9.0f);

    float acc[4][8];
    #pragma unroll
    for (int j = 0; j < 4; j++)
        #pragma unroll
        for (int b = 0; b < 8; b++) acc[j][b] = 0.0f;

    if (ch < 36) {
        int i0 = ch * 28;
        stage_rows<14>(w_pos, w_neg, n_param, phi_s, coef_s, i0,      j0, tid, jq, bbase, cG, acc);
        stage_rows<14>(w_pos, w_neg, n_param, phi_s, coef_s, i0 + 14, j0, tid, jq, bbase, cG, acc);
    } else {
        stage_rows<8>(w_pos, w_neg, n_param, phi_s, coef_s, 1008, j0, tid, jq, bbase, cG, acc);
        stage_rows<8>(w_pos, w_neg, n_param, phi_s, coef_s, 1016, j0, tid, jq, bbase, cG, acc);
    }

    float* outp = &g_partial[ch * (BATCH * NOUT)];
    #pragma unroll
    for (int b = 0; b < 8; b++) {
        float4 v = make_float4(acc[0][b], acc[1][b], acc[2][b], acc[3][b]);
        *reinterpret_cast<float4*>(&outp[(bbase + b) * NOUT + j0 + jq * 4]) = v;
    }

    // ================= gate2 + in-place reduction (L2-hot) =================
    global_gate(&g_gate2, tid);

    if (g < OUTF4) {
        const float4* gp = reinterpret_cast<const float4*>(g_partial);
        float4 s = make_float4(0.0f, 0.0f, 0.0f, 0.0f);
        #pragma unroll
        for (int c = 0; c < NCH; c++) {               // compile-time: full unroll, MLP=37
            float4 v = gp[c * OUTF4 + g];
            s.x += v.x; s.y += v.y; s.z += v.z; s.w += v.w;
        }
        // exact bias term: vr = 2 -> vr^(lg2 n + 1) = 2n -> term = (|b|+cG)*n
        const int j = (g * 4) & (NOUT - 1);
        float4 bp = *reinterpret_cast<const float4*>(&b_pos[j]);
        float4 bn = *reinterpret_cast<const float4*>(&b_neg[j]);
        const float* nrow = n_param + (size_t)NIN * (2 * NOUT);
        float4 n0 = *reinterpret_cast<const float4*>(&nrow[2 * j]);
        float4 n1 = *reinterpret_cast<const float4*>(&nrow[2 * j + 4]);
        s.x += (fabsf(bp.x) + cG) * n0.x - (fabsf(bn.x) + cG) * n0.y;
        s.y += (fabsf(bp.y) + cG) * n0.z - (fabsf(bn.y) + cG) * n0.w;
        s.z += (fabsf(bp.z) + cG) * n1.x - (fabsf(bn.z) + cG) * n1.y;
        s.w += (fabsf(bp.w) + cG) * n1.z - (fabsf(bn.w) + cG) * n1.w;
        out[g] = s;
    }
}

// ---------------------------------------------------------------------------
extern "C" void kernel_launch(void* const* d_in, const int* in_sizes, int n_in,
                              void* d_out, int out_size) {
    const float* x       = (const float*)d_in[0];
    const float* w_pos   = (const float*)d_in[1];
    const float* w_neg   = (const float*)d_in[2];
    const float* b_pos   = (const float*)d_in[3];
    const float* b_neg   = (const float*)d_in[4];
    const float* n_param = (const float*)d_in[5];

    dim3 grid(NJT, NCH);     // 8 x 37 = 296 = 148*2, all co-resident at occ 2
    k_all<<<grid, 256>>>((const float4*)x, w_pos, w_neg, n_param,
                         b_pos, b_neg, (float4*)d_out);
}